// round 6
// baseline (speedup 1.0000x reference)
#include <cuda_runtime.h>
#include <math.h>
#include <float.h>

// Problem dims (fixed by the dataset problem)
#define Bn 4
#define Pn 64
#define Dn 768
#define Nn 2048
#define Rn 12
#define Kn 16
#define Mn (Bn * Pn)   // 256 query rows
#define SPLITK 4       // split-K factor for k_out

// Scratch (device globals — no allocation allowed)
__device__ float g_keys[Nn * Dn];          // normalized keys  (6 MB)
__device__ float g_asum[Nn * Nn];          // sum over R of adjacency (16 MB)
__device__ float g_scores[Mn * Nn];        // (2 MB)
__device__ float g_nei[Mn * Nn];           // (2 MB)
__device__ float g_outp[SPLITK][Mn * Dn];  // split-K partials (3 MB)

// ---------------------------------------------------------------------------
// Kernel 1: row-normalize keys_param -> g_keys
// ---------------------------------------------------------------------------
__global__ __launch_bounds__(256) void k_norm(const float* __restrict__ kp) {
    int n   = blockIdx.x;
    int tid = threadIdx.x;
    const float* row = kp + (size_t)n * Dn;

    float v0 = row[tid];
    float v1 = row[tid + 256];
    float v2 = row[tid + 512];
    float s  = v0 * v0 + v1 * v1 + v2 * v2;

    #pragma unroll
    for (int o = 16; o; o >>= 1) s += __shfl_xor_sync(0xffffffffu, s, o);

    __shared__ float red[8];
    __shared__ float sinv;
    if ((tid & 31) == 0) red[tid >> 5] = s;
    __syncthreads();
    if (tid == 0) {
        float t = 0.f;
        #pragma unroll
        for (int i = 0; i < 8; i++) t += red[i];
        sinv = rsqrtf(t + 1e-12f);
    }
    __syncthreads();
    float inv = sinv;
    float* out = g_keys + (size_t)n * Dn;
    out[tid]       = v0 * inv;
    out[tid + 256] = v1 * inv;
    out[tid + 512] = v2 * inv;
}

// ---------------------------------------------------------------------------
// Kernel 2 (FUSED): blocks 0..127 = scores NT-SGEMM (compute-bound),
// blocks 128..4223 = A_sum reduction over R (DRAM-bound).  The two roles
// co-reside on SMs so HBM streaming overlaps FMA issue.
// ---------------------------------------------------------------------------
__global__ __launch_bounds__(256) void k_fused(const float* __restrict__ A,
                                               const float4* __restrict__ adj) {
    if (blockIdx.x >= 128) {
        // ---- A_sum role: one float4 per thread over 12 slices ----
        size_t i = (size_t)(blockIdx.x - 128) * 256 + threadIdx.x;
        float4 s = adj[i];
        #pragma unroll
        for (int r = 1; r < Rn; r++) {
            float4 t = adj[i + (size_t)r * (Nn * Nn / 4)];
            s.x += t.x; s.y += t.y; s.z += t.z; s.w += t.w;
        }
        ((float4*)g_asum)[i] = s;
        return;
    }

    // ---- scores role: BM=64, BN=64, BK=16, 4x4/thread, reg double-buffer ----
    const int BM = 64, BN = 64, BK = 16;
    __shared__ float As[BK][BM + 4];
    __shared__ float Bs[BK][BN + 4];

    int tid = threadIdx.x;
    int m0 = (blockIdx.x >> 5) * BM;   // 0..3  -> 0..192
    int n0 = (blockIdx.x & 31) * BN;   // 0..31 -> 0..1984

    int lr = tid >> 2;          // 0..63
    int lk = (tid & 3) * 4;     // 0,4,8,12
    int rm = (tid >> 4) * 4;    // 0..60
    int rn = (tid & 15) * 4;    // 0..60

    float acc[4][4];
    #pragma unroll
    for (int i = 0; i < 4; i++)
        #pragma unroll
        for (int j = 0; j < 4; j++) acc[i][j] = 0.f;

    float4 a = *(const float4*)&A[(size_t)(m0 + lr) * Dn + lk];
    float4 b = *(const float4*)&g_keys[(size_t)(n0 + lr) * Dn + lk];

    for (int kb = 0; kb < Dn; kb += BK) {
        As[lk + 0][lr] = a.x; As[lk + 1][lr] = a.y;
        As[lk + 2][lr] = a.z; As[lk + 3][lr] = a.w;
        Bs[lk + 0][lr] = b.x; Bs[lk + 1][lr] = b.y;
        Bs[lk + 2][lr] = b.z; Bs[lk + 3][lr] = b.w;
        __syncthreads();

        if (kb + BK < Dn) {
            a = *(const float4*)&A[(size_t)(m0 + lr) * Dn + kb + BK + lk];
            b = *(const float4*)&g_keys[(size_t)(n0 + lr) * Dn + kb + BK + lk];
        }

        #pragma unroll
        for (int kk = 0; kk < BK; kk++) {
            float4 ra = *(float4*)&As[kk][rm];
            float4 rb = *(float4*)&Bs[kk][rn];
            acc[0][0] += ra.x * rb.x; acc[0][1] += ra.x * rb.y;
            acc[0][2] += ra.x * rb.z; acc[0][3] += ra.x * rb.w;
            acc[1][0] += ra.y * rb.x; acc[1][1] += ra.y * rb.y;
            acc[1][2] += ra.y * rb.z; acc[1][3] += ra.y * rb.w;
            acc[2][0] += ra.z * rb.x; acc[2][1] += ra.z * rb.y;
            acc[2][2] += ra.z * rb.z; acc[2][3] += ra.z * rb.w;
            acc[3][0] += ra.w * rb.x; acc[3][1] += ra.w * rb.y;
            acc[3][2] += ra.w * rb.z; acc[3][3] += ra.w * rb.w;
        }
        __syncthreads();
    }

    #pragma unroll
    for (int i = 0; i < 4; i++) {
        float4 v = make_float4(acc[i][0], acc[i][1], acc[i][2], acc[i][3]);
        *(float4*)&g_scores[(size_t)(m0 + rm + i) * Nn + n0 + rn] = v;
    }
}

// ---------------------------------------------------------------------------
// Kernel 3 (FUSED): top-16 + softmax + gather.  One warp per row for top-k
// (u64 packed max-tree, no barriers), then the 128-thread block gathers
// nei[m,:] = sum_k w*A_sum[idx,:] for its 4 rows.
// Packing: (orderable(val) << 32) | ~gidx  ->  u64 max == (val desc, idx asc).
// ---------------------------------------------------------------------------
__global__ __launch_bounds__(128) void k_topk_gather() {
    __shared__ float ws[4][Kn];
    __shared__ int   is[4][Kn];

    int wl   = threadIdx.x >> 5;
    int lane = threadIdx.x & 31;
    int m    = blockIdx.x * 4 + wl;
    const float* row = g_scores + (size_t)m * Nn;

    // load + pack 64 values per lane (coalesced)
    unsigned long long p[64];
    #pragma unroll
    for (int j = 0; j < 64; j++) {
        unsigned fb  = __float_as_uint(row[j * 32 + lane]);
        unsigned ord = (fb & 0x80000000u) ? ~fb : (fb | 0x80000000u);
        p[j] = ((unsigned long long)ord << 32)
             | (unsigned long long)(~(unsigned)(j * 32 + lane));
    }

    #pragma unroll 1
    for (int it = 0; it < Kn; it++) {
        // 6-level max tree over 64 register values (shallow dep chain)
        unsigned long long t[32];
        #pragma unroll
        for (int j = 0; j < 32; j++)
            t[j] = (p[2 * j] > p[2 * j + 1]) ? p[2 * j] : p[2 * j + 1];
        #pragma unroll
        for (int s = 16; s >= 1; s >>= 1)
            #pragma unroll
            for (int j = 0; j < s; j++)
                if (t[j + s] > t[j]) t[j] = t[j + s];
        unsigned long long best = t[0];

        // warp max
        #pragma unroll
        for (int o = 16; o; o >>= 1) {
            unsigned long long ob = __shfl_xor_sync(0xffffffffu, best, o);
            if (ob > best) best = ob;
        }

        unsigned gidx = ~(unsigned)best;
        unsigned ord  = (unsigned)(best >> 32);

        if (lane == 0) {
            ws[wl][it] = __uint_as_float((ord & 0x80000000u) ? (ord & 0x7FFFFFFFu)
                                                             : ~ord);
            is[wl][it] = (int)gidx;
        }
        // permanently kill the winner in its owning lane
        if (lane == (gidx & 31)) {
            int kj = (int)(gidx >> 5);
            #pragma unroll
            for (int j = 0; j < 64; j++)
                if (j == kj) p[j] = 0ULL;
        }
    }
    __syncwarp();

    // softmax over the 16 winners (ws[wl][0] is the max)
    float tv[Kn];
    #pragma unroll
    for (int i = 0; i < Kn; i++) tv[i] = ws[wl][i];
    float mx = tv[0], sum = 0.f;
    #pragma unroll
    for (int i = 0; i < Kn; i++) sum += expf(tv[i] - mx);
    __syncwarp();
    if (lane < Kn) ws[wl][lane] = expf(tv[lane] - mx) / sum;
    __syncthreads();

    // gather: nei[mr,:] = sum_k w * A_sum[idx,:]   (A_sum rows are L2-hot)
    for (int r = 0; r < 4; r++) {
        int mr = blockIdx.x * 4 + r;
        float wk[Kn]; int ik[Kn];
        #pragma unroll
        for (int k = 0; k < Kn; k++) { wk[k] = ws[r][k]; ik[k] = is[r][k]; }
        for (int c = threadIdx.x; c < Nn / 4; c += 128) {
            float4 acc = make_float4(0.f, 0.f, 0.f, 0.f);
            #pragma unroll
            for (int k = 0; k < Kn; k++) {
                float4 v = ((const float4*)(g_asum + (size_t)ik[k] * Nn))[c];
                acc.x += wk[k] * v.x; acc.y += wk[k] * v.y;
                acc.z += wk[k] * v.z; acc.w += wk[k] * v.w;
            }
            ((float4*)(g_nei + (size_t)mr * Nn))[c] = acc;
        }
    }
}

// ---------------------------------------------------------------------------
// Kernel 4: out = nei (256x2048) @ keys (2048x768)  [NN SGEMM, split-K,
// register double buffering].  Grid (12, 4, SPLITK) = 192 blocks.
// ---------------------------------------------------------------------------
__global__ __launch_bounds__(256) void k_out() {
    const int BM = 64, BN = 64, BK = 16;
    const int KC = Nn / SPLITK;   // 512
    __shared__ float As[BK][BM + 4];
    __shared__ float Bs[BK][BN + 4];

    int tid = threadIdx.x;
    int m0 = blockIdx.y * BM;
    int n0 = blockIdx.x * BN;
    int kbase = blockIdx.z * KC;

    int lr = tid >> 2;
    int lk = (tid & 3) * 4;
    int br = tid >> 4;
    int bc = (tid & 15) * 4;
    int rm = (tid >> 4) * 4;
    int rn = (tid & 15) * 4;

    float acc[4][4];
    #pragma unroll
    for (int i = 0; i < 4; i++)
        #pragma unroll
        for (int j = 0; j < 4; j++) acc[i][j] = 0.f;

    float4 a = *(const float4*)&g_nei[(size_t)(m0 + lr) * Nn + kbase + lk];
    float4 b = *(const float4*)&g_keys[(size_t)(kbase + br) * Dn + n0 + bc];

    for (int kb = kbase; kb < kbase + KC; kb += BK) {
        As[lk + 0][lr] = a.x; As[lk + 1][lr] = a.y;
        As[lk + 2][lr] = a.z; As[lk + 3][lr] = a.w;
        *(float4*)&Bs[br][bc] = b;
        __syncthreads();

        if (kb + BK < kbase + KC) {
            a = *(const float4*)&g_nei[(size_t)(m0 + lr) * Nn + kb + BK + lk];
            b = *(const float4*)&g_keys[(size_t)(kb + BK + br) * Dn + n0 + bc];
        }

        #pragma unroll
        for (int kk = 0; kk < BK; kk++) {
            float4 ra = *(float4*)&As[kk][rm];
            float4 rb = *(float4*)&Bs[kk][rn];
            acc[0][0] += ra.x * rb.x; acc[0][1] += ra.x * rb.y;
            acc[0][2] += ra.x * rb.z; acc[0][3] += ra.x * rb.w;
            acc[1][0] += ra.y * rb.x; acc[1][1] += ra.y * rb.y;
            acc[1][2] += ra.y * rb.z; acc[1][3] += ra.y * rb.w;
            acc[2][0] += ra.z * rb.x; acc[2][1] += ra.z * rb.y;
            acc[2][2] += ra.z * rb.z; acc[2][3] += ra.z * rb.w;
            acc[3][0] += ra.w * rb.x; acc[3][1] += ra.w * rb.y;
            acc[3][2] += ra.w * rb.z; acc[3][3] += ra.w * rb.w;
        }
        __syncthreads();
    }

    float* P = g_outp[blockIdx.z];
    #pragma unroll
    for (int i = 0; i < 4; i++) {
        float4 v = make_float4(acc[i][0], acc[i][1], acc[i][2], acc[i][3]);
        *(float4*)&P[(size_t)(m0 + rm + i) * Dn + n0 + rn] = v;
    }
}

// ---------------------------------------------------------------------------
// Kernel 5: out = sum of SPLITK partials
// ---------------------------------------------------------------------------
__global__ __launch_bounds__(256) void k_reduce(float4* __restrict__ out) {
    int i = blockIdx.x * 256 + threadIdx.x;
    float4 r = ((const float4*)g_outp[0])[i];
    #pragma unroll
    for (int s = 1; s < SPLITK; s++) {
        float4 t = ((const float4*)g_outp[s])[i];
        r.x += t.x; r.y += t.y; r.z += t.z; r.w += t.w;
    }
    out[i] = r;
}

// ---------------------------------------------------------------------------
// Host launcher — default stream, graph-capturable.
// Inputs: positions, keys_param, adjacency, k (fixed 16).
// ---------------------------------------------------------------------------
extern "C" void kernel_launch(void* const* d_in, const int* in_sizes, int n_in,
                              void* d_out, int out_size) {
    (void)in_sizes; (void)n_in; (void)out_size;
    const float* positions = (const float*)d_in[0];
    const float* keys_p    = (const float*)d_in[1];
    const float* adjacency = (const float*)d_in[2];
    float* out = (float*)d_out;

    k_norm       <<<Nn, 256>>>(keys_p);
    k_fused      <<<128 + (Nn * Nn / 4) / 256, 256>>>(positions,
                                                      (const float4*)adjacency);
    k_topk_gather<<<Mn / 4, 128>>>();
    k_out        <<<dim3(Dn / 64, Mn / 64, SPLITK), 256>>>();
    k_reduce     <<<(Mn * Dn / 4) / 256, 256>>>((float4*)out);
}